// round 7
// baseline (speedup 1.0000x reference)
#include <cuda_runtime.h>
#include <cuda_fp16.h>
#include <stdint.h>

#define WST 72                       // padded smem stride (halfs) -> conflict-free ldmatrix
#define MAT_HALFS (64 * WST)         // 4608 halfs per 64x64 matrix
#define NMAT 11
#define W_HALFS (NMAT * MAT_HALFS)
#define FBYTES (832 * 4)
#define AL_WORDS (3 * 8 * 32 * 32)   // [layer][warp][idx][lane] uint32 = 96 KB
#define SMEM_BYTES (W_HALFS * 2 + FBYTES + AL_WORDS * 4)

// float-region offsets (in floats)
#define F_M1W 0
#define F_M1B 192
#define F_SW  256
#define F_SB  384
#define F_M2B 448
#define F_M3B 512
#define F_A0B 576
#define F_A1B 640
#define F_A2B 704
#define F_EW  768

// matrix slots in smem
#define M_M2 0
#define M_M3 1
#define M_A0 2
#define M_A1 3
#define M_A2 4
#define M_C0 5
#define M_R0 8

struct Params {
    const float *x, *t, *beta, *nu, *rho;
    const float *start_w, *start_b, *end_w, *end_b;
    const float *m1_w, *m1_b, *m2_w, *m2_b, *m3_w, *m3_b;
    const float *a0_w, *a0_b, *a1_w, *a1_b, *a2_w, *a2_b;
    const float *col0, *col1, *col2, *row0, *row1, *row2;
    float* out;
    int ntiles;
    int B;
};

// HW tanh (MUFU.TANH)
__device__ __forceinline__ float tanh_fast(float x) {
    float y;
    asm("tanh.approx.f32 %0, %1;" : "=f"(y) : "f"(x));
    return y;
}

__device__ __forceinline__ uint32_t pack2(float lo, float hi) {
    __half2 h = __floats2half2_rn(lo, hi);
    return *reinterpret_cast<uint32_t*>(&h);
}
__device__ __forceinline__ float2 unpack2(uint32_t v) {
    __half2 h = *reinterpret_cast<__half2*>(&v);
    return __half22float2(h);
}

__device__ __forceinline__ void mma16816(float* c, const uint32_t* a, uint32_t b0, uint32_t b1) {
    asm volatile(
        "mma.sync.aligned.m16n8k16.row.col.f32.f16.f16.f32 "
        "{%0,%1,%2,%3}, {%4,%5,%6,%7}, {%8,%9}, {%0,%1,%2,%3};\n"
        : "+f"(c[0]), "+f"(c[1]), "+f"(c[2]), "+f"(c[3])
        : "r"(a[0]), "r"(a[1]), "r"(a[2]), "r"(a[3]), "r"(b0), "r"(b1));
}

__device__ __forceinline__ void ldsm4t(uint32_t& r0, uint32_t& r1, uint32_t& r2, uint32_t& r3,
                                       uint32_t addr) {
    asm volatile("ldmatrix.sync.aligned.m8n8.x4.trans.shared.b16 {%0,%1,%2,%3}, [%4];\n"
                 : "=r"(r0), "=r"(r1), "=r"(r2), "=r"(r3)
                 : "r"(addr));
}

// Dual-tile GEMM: C[h][8][4] = A[h](16x64 frags) @ W(64x64), h = 0,1.
// One ldmatrix B-fragment feeds MMAs of BOTH row halves.
__device__ __forceinline__ void gemm64x2(float C[2][8][4], const uint32_t A[2][4][4],
                                         const __half* W, int lane) {
#pragma unroll
    for (int h = 0; h < 2; h++)
#pragma unroll
        for (int nt = 0; nt < 8; nt++)
#pragma unroll
            for (int q = 0; q < 4; q++) C[h][nt][q] = 0.f;

    uint32_t base = (uint32_t)__cvta_generic_to_shared(
        W + (lane & 15) * WST + ((lane & 16) ? 8 : 0));
#pragma unroll
    for (int nt2 = 0; nt2 < 4; nt2++) {
#pragma unroll
        for (int kb = 0; kb < 4; kb++) {
            uint32_t b0, b1, b2, b3;
            ldsm4t(b0, b1, b2, b3, base + (uint32_t)((kb * 16 * WST + nt2 * 16) * 2));
            mma16816(C[0][nt2 * 2],     A[0][kb], b0, b1);
            mma16816(C[0][nt2 * 2 + 1], A[0][kb], b2, b3);
            mma16816(C[1][nt2 * 2],     A[1][kb], b0, b1);
            mma16816(C[1][nt2 * 2 + 1], A[1][kb], b2, b3);
        }
    }
}

__device__ __forceinline__ void add_bias2(float C[2][8][4], const float* bias, int tig) {
#pragma unroll
    for (int h = 0; h < 2; h++)
#pragma unroll
        for (int nt = 0; nt < 8; nt++) {
            float b0 = bias[nt * 8 + tig * 2], b1 = bias[nt * 8 + tig * 2 + 1];
            C[h][nt][0] += b0; C[h][nt][1] += b1; C[h][nt][2] += b0; C[h][nt][3] += b1;
        }
}

// C (m16n8 frags) -> A (m16k16 frags), tanh applied
__device__ __forceinline__ void repack_tanh2(const float C[2][8][4], uint32_t A[2][4][4]) {
#pragma unroll
    for (int h = 0; h < 2; h++)
#pragma unroll
        for (int kb = 0; kb < 4; kb++) {
            A[h][kb][0] = pack2(tanh_fast(C[h][2 * kb][0]),     tanh_fast(C[h][2 * kb][1]));
            A[h][kb][1] = pack2(tanh_fast(C[h][2 * kb][2]),     tanh_fast(C[h][2 * kb][3]));
            A[h][kb][2] = pack2(tanh_fast(C[h][2 * kb + 1][0]), tanh_fast(C[h][2 * kb + 1][1]));
            A[h][kb][3] = pack2(tanh_fast(C[h][2 * kb + 1][2]), tanh_fast(C[h][2 * kb + 1][3]));
        }
}
__device__ __forceinline__ void repack_id2(const float C[2][8][4], uint32_t A[2][4][4]) {
#pragma unroll
    for (int h = 0; h < 2; h++)
#pragma unroll
        for (int kb = 0; kb < 4; kb++) {
            A[h][kb][0] = pack2(C[h][2 * kb][0],     C[h][2 * kb][1]);
            A[h][kb][1] = pack2(C[h][2 * kb][2],     C[h][2 * kb][3]);
            A[h][kb][2] = pack2(C[h][2 * kb + 1][0], C[h][2 * kb + 1][1]);
            A[h][kb][3] = pack2(C[h][2 * kb + 1][2], C[h][2 * kb + 1][3]);
        }
}

__global__ void __launch_bounds__(256, 1)
pinn_kernel(Params p) {
    extern __shared__ char smem_raw[];
    __half* smW = reinterpret_cast<__half*>(smem_raw);
    float* smF = reinterpret_cast<float*>(smem_raw + W_HALFS * 2);
    uint32_t* smAL = reinterpret_cast<uint32_t*>(smem_raw + W_HALFS * 2 + FBYTES);
    const int tid = threadIdx.x;

    // ---- fold in the pass-through copy (24576 floats = 6144 float4) ----
    if (blockIdx.x < 24) {
        int i = blockIdx.x * 256 + tid;
        int j = i & 1023;
        int m = i >> 10;
        const float* srcs[6] = {p.col0, p.col1, p.col2, p.row0, p.row1, p.row2};
        const float4* s4 = reinterpret_cast<const float4*>(srcs[m]) + j;
        reinterpret_cast<float4*>(p.out + p.B)[i] = *s4;
    }

    // ---- stage weights (fp32 -> fp16, padded stride) ----
    {
        const float* gsrc[NMAT] = {p.m2_w, p.m3_w, p.a0_w, p.a1_w, p.a2_w,
                                   p.col0, p.col1, p.col2, p.row0, p.row1, p.row2};
#pragma unroll
        for (int m = 0; m < NMAT; m++) {
            const float* src = gsrc[m];
            __half* dst = smW + m * MAT_HALFS;
            for (int i = tid; i < 4096; i += 256)
                dst[(i >> 6) * WST + (i & 63)] = __float2half_rn(src[i]);
        }
        if (tid < 192) smF[F_M1W + tid] = p.m1_w[tid];
        if (tid < 128) smF[F_SW + tid] = p.start_w[tid];
        if (tid < 64) {
            smF[F_M1B + tid] = p.m1_b[tid];
            smF[F_SB + tid]  = p.start_b[tid];
            smF[F_M2B + tid] = p.m2_b[tid];
            smF[F_M3B + tid] = p.m3_b[tid];
            smF[F_A0B + tid] = p.a0_b[tid];
            smF[F_A1B + tid] = p.a1_b[tid];
            smF[F_A2B + tid] = p.a2_b[tid];
            smF[F_EW  + tid] = p.end_w[tid];
        }
    }
    __syncthreads();

    const int lane = tid & 31, warp = tid >> 5;
    const int g = lane >> 2, tig = lane & 3;
    const float eb = p.end_b[0];
    // alpha scratch: [l][warp][idx(0..31)][lane] — warp-private, conflict-free
    uint32_t* alw = smAL + warp * (32 * 32) + lane;

    for (int tile = blockIdx.x; tile < p.ntiles; tile += gridDim.x) {
        const int rowbase = tile * 256 + warp * 32;   // 32 rows per warp

        float C[2][8][4];

        // ================= PHASE 1: hypernet -> alphas to SMEM =================
        {
            uint32_t Mst[2][4][4];
#pragma unroll
            for (int h = 0; h < 2; h++) {
                const int rlo = rowbase + h * 16 + g, rhi = rlo + 8;
                float b0 = p.beta[rlo], b1 = p.beta[rhi];
                float n0 = p.nu[rlo],   n1 = p.nu[rhi];
                float r0 = p.rho[rlo],  r1 = p.rho[rhi];
#pragma unroll
                for (int kb = 0; kb < 4; kb++) {
                    int j0 = kb * 16 + tig * 2;
#pragma unroll
                    for (int hf = 0; hf < 2; hf++) {
                        int j = j0 + hf * 8;
                        float w0a = smF[F_M1W + j],        w0b = smF[F_M1W + j + 1];
                        float w1a = smF[F_M1W + 64 + j],   w1b = smF[F_M1W + 64 + j + 1];
                        float w2a = smF[F_M1W + 128 + j],  w2b = smF[F_M1W + 128 + j + 1];
                        float ba  = smF[F_M1B + j],        bb  = smF[F_M1B + j + 1];
                        Mst[h][kb][hf * 2 + 0] = pack2(tanh_fast(b0 * w0a + n0 * w1a + r0 * w2a + ba),
                                                       tanh_fast(b0 * w0b + n0 * w1b + r0 * w2b + bb));
                        Mst[h][kb][hf * 2 + 1] = pack2(tanh_fast(b1 * w0a + n1 * w1a + r1 * w2a + ba),
                                                       tanh_fast(b1 * w0b + n1 * w1b + r1 * w2b + bb));
                    }
                }
            }

            gemm64x2(C, Mst, smW + M_M2 * MAT_HALFS, lane);
            add_bias2(C, smF + F_M2B, tig);
            repack_tanh2(C, Mst);
            gemm64x2(C, Mst, smW + M_M3 * MAT_HALFS, lane);
            add_bias2(C, smF + F_M3B, tig);
            repack_tanh2(C, Mst);

            // 3 alpha heads -> relu -> pack -> SMEM (warp-private, no sync needed)
#pragma unroll
            for (int l = 0; l < 3; l++) {
                gemm64x2(C, Mst, smW + (M_A0 + l) * MAT_HALFS, lane);
                add_bias2(C, smF + F_A0B + 64 * l, tig);
                uint32_t* dst = alw + l * (8 * 32 * 32);
#pragma unroll
                for (int h = 0; h < 2; h++)
#pragma unroll
                    for (int nt = 0; nt < 8; nt++) {
                        dst[(h * 16 + nt * 2 + 0) * 32] =
                            pack2(fmaxf(C[h][nt][0], 0.f), fmaxf(C[h][nt][1], 0.f));
                        dst[(h * 16 + nt * 2 + 1) * 32] =
                            pack2(fmaxf(C[h][nt][2], 0.f), fmaxf(C[h][nt][3], 0.f));
                    }
            }
        }

        // ================= PHASE 2: main chain (Mst dead) =================
        uint32_t A[2][4][4];
#pragma unroll
        for (int h = 0; h < 2; h++) {
            const int rlo = rowbase + h * 16 + g, rhi = rlo + 8;
            float x0 = p.x[rlo], x1 = p.x[rhi];
            float t0 = p.t[rlo], t1 = p.t[rhi];
#pragma unroll
            for (int kb = 0; kb < 4; kb++) {
                int j0 = kb * 16 + tig * 2;
#pragma unroll
                for (int hf = 0; hf < 2; hf++) {
                    int j = j0 + hf * 8;
                    float w0a = smF[F_SW + j],      w0b = smF[F_SW + j + 1];
                    float w1a = smF[F_SW + 64 + j], w1b = smF[F_SW + 64 + j + 1];
                    float ba  = smF[F_SB + j],      bb  = smF[F_SB + j + 1];
                    A[h][kb][hf * 2 + 0] = pack2(tanh_fast(x0 * w0a + t0 * w1a + ba),
                                                 tanh_fast(x0 * w0b + t0 * w1b + bb));
                    A[h][kb][hf * 2 + 1] = pack2(tanh_fast(x1 * w0a + t1 * w1a + ba),
                                                 tanh_fast(x1 * w0b + t1 * w1b + bb));
                }
            }
        }

#pragma unroll
        for (int l = 0; l < 3; l++) {
            gemm64x2(C, A, smW + (M_C0 + l) * MAT_HALFS, lane);
            const uint32_t* src = alw + l * (8 * 32 * 32);
#pragma unroll
            for (int h = 0; h < 2; h++)
#pragma unroll
                for (int nt = 0; nt < 8; nt++) {
                    float2 f0 = unpack2(src[(h * 16 + nt * 2 + 0) * 32]);
                    float2 f1 = unpack2(src[(h * 16 + nt * 2 + 1) * 32]);
                    C[h][nt][0] *= f0.x; C[h][nt][1] *= f0.y;
                    C[h][nt][2] *= f1.x; C[h][nt][3] *= f1.y;
                }
            repack_id2(C, A);
            gemm64x2(C, A, smW + (M_R0 + l) * MAT_HALFS, lane);
            repack_tanh2(C, A);
        }

        // ---- out = h @ end_w + end_b ----
#pragma unroll
        for (int h = 0; h < 2; h++) {
            const int rlo = rowbase + h * 16 + g, rhi = rlo + 8;
            float slo = 0.f, shi = 0.f;
#pragma unroll
            for (int kb = 0; kb < 4; kb++) {
                int j0 = kb * 16 + tig * 2;
                float2 f;
                f = unpack2(A[h][kb][0]); slo += f.x * smF[F_EW + j0]     + f.y * smF[F_EW + j0 + 1];
                f = unpack2(A[h][kb][1]); shi += f.x * smF[F_EW + j0]     + f.y * smF[F_EW + j0 + 1];
                f = unpack2(A[h][kb][2]); slo += f.x * smF[F_EW + j0 + 8] + f.y * smF[F_EW + j0 + 9];
                f = unpack2(A[h][kb][3]); shi += f.x * smF[F_EW + j0 + 8] + f.y * smF[F_EW + j0 + 9];
            }
            slo += __shfl_xor_sync(0xFFFFFFFFu, slo, 1);
            slo += __shfl_xor_sync(0xFFFFFFFFu, slo, 2);
            shi += __shfl_xor_sync(0xFFFFFFFFu, shi, 1);
            shi += __shfl_xor_sync(0xFFFFFFFFu, shi, 2);
            if (tig == 0) {
                p.out[rlo] = slo + eb;
                p.out[rhi] = shi + eb;
            }
        }
    }
}

extern "C" void kernel_launch(void* const* d_in, const int* in_sizes, int n_in,
                              void* d_out, int out_size) {
    (void)n_in; (void)out_size;
    Params p;
    p.x       = (const float*)d_in[0];
    p.t       = (const float*)d_in[1];
    p.beta    = (const float*)d_in[2];
    p.nu      = (const float*)d_in[3];
    p.rho     = (const float*)d_in[4];
    p.start_w = (const float*)d_in[5];
    p.start_b = (const float*)d_in[6];
    p.end_w   = (const float*)d_in[7];
    p.end_b   = (const float*)d_in[8];
    p.m1_w    = (const float*)d_in[9];
    p.m1_b    = (const float*)d_in[10];
    p.m2_w    = (const float*)d_in[11];
    p.m2_b    = (const float*)d_in[12];
    p.m3_w    = (const float*)d_in[13];
    p.m3_b    = (const float*)d_in[14];
    p.a0_w    = (const float*)d_in[15];
    p.a0_b    = (const float*)d_in[16];
    p.a1_w    = (const float*)d_in[17];
    p.a1_b    = (const float*)d_in[18];
    p.a2_w    = (const float*)d_in[19];
    p.a2_b    = (const float*)d_in[20];
    p.col0    = (const float*)d_in[21];
    p.col1    = (const float*)d_in[22];
    p.col2    = (const float*)d_in[23];
    p.row0    = (const float*)d_in[24];
    p.row1    = (const float*)d_in[25];
    p.row2    = (const float*)d_in[26];
    p.out     = (float*)d_out;

    p.B = in_sizes[0];
    p.ntiles = p.B / 256;   // 256 rows per CTA tile

    int dev = 0, nsm = 148;
    cudaGetDevice(&dev);
    cudaDeviceGetAttribute(&nsm, cudaDevAttrMultiProcessorCount, dev);
    int grid = nsm < 24 ? 24 : nsm;   // >=24 so the folded copy covers all 6 matrices
    if (grid > p.ntiles) grid = p.ntiles;

    cudaFuncSetAttribute(pinn_kernel, cudaFuncAttributeMaxDynamicSharedMemorySize, SMEM_BYTES);
    pinn_kernel<<<grid, 256, SMEM_BYTES>>>(p);
}

// round 8
// speedup vs baseline: 1.2365x; 1.2365x over previous
#include <cuda_runtime.h>
#include <cuda_fp16.h>
#include <stdint.h>

#define WST 72                       // padded smem stride (halfs) -> conflict-free ldmatrix
#define MAT_HALFS (64 * WST)         // 4608 halfs per 64x64 matrix
#define NMAT 11
#define W_HALFS (NMAT * MAT_HALFS)
#define F32_FLOATS 512
#define PB_WORDS 160
#define SMEM_BYTES (W_HALFS * 2 + F32_FLOATS * 4 + PB_WORDS * 4)

// f32 scalar region offsets (floats)
#define F_M1W 0
#define F_M1B 192
#define F_SW  256
#define F_SB  384
#define F_EW  448
// packed f16x2 bias region offsets (uint32 words)
#define PB_M2 0
#define PB_M3 32
#define PB_A0 64     // +32 per alpha head

// matrix slots in smem
#define M_M2 0
#define M_M3 1
#define M_A0 2
#define M_A1 3
#define M_A2 4
#define M_C0 5
#define M_R0 8

struct Params {
    const float *x, *t, *beta, *nu, *rho;
    const float *start_w, *start_b, *end_w, *end_b;
    const float *m1_w, *m1_b, *m2_w, *m2_b, *m3_w, *m3_b;
    const float *a0_w, *a0_b, *a1_w, *a1_b, *a2_w, *a2_b;
    const float *col0, *col1, *col2, *row0, *row1, *row2;
    float* out;
    int ntiles;
    int B;
};

__device__ __forceinline__ uint32_t pack2(float lo, float hi) {
    __half2 h = __floats2half2_rn(lo, hi);
    return *reinterpret_cast<uint32_t*>(&h);
}
__device__ __forceinline__ float2 unpack2(uint32_t v) {
    __half2 h = *reinterpret_cast<__half2*>(&v);
    return __half22float2(h);
}
// HW tanh on packed f16x2 (one MUFU op for two values)
__device__ __forceinline__ uint32_t htanh2(uint32_t v) {
    uint32_t y;
    asm("tanh.approx.f16x2 %0, %1;" : "=r"(y) : "r"(v));
    return y;
}
__device__ __forceinline__ uint32_t hadd2u(uint32_t a, uint32_t b) {
    __half2 r = __hadd2(*reinterpret_cast<__half2*>(&a), *reinterpret_cast<__half2*>(&b));
    return *reinterpret_cast<uint32_t*>(&r);
}
__device__ __forceinline__ uint32_t hmul2u(uint32_t a, uint32_t b) {
    __half2 r = __hmul2(*reinterpret_cast<__half2*>(&a), *reinterpret_cast<__half2*>(&b));
    return *reinterpret_cast<uint32_t*>(&r);
}
__device__ __forceinline__ uint32_t hrelu2(uint32_t a) {
    __half2 z = __float2half2_rn(0.f);
    __half2 r = __hmax2(*reinterpret_cast<__half2*>(&a), z);
    return *reinterpret_cast<uint32_t*>(&r);
}

// f16-accumulator MMA: C/D are 2 regs of f16x2 ({c0,c1},{c2,c3})
__device__ __forceinline__ void mma16816h(uint32_t* c, const uint32_t* a, uint32_t b0, uint32_t b1) {
    asm volatile(
        "mma.sync.aligned.m16n8k16.row.col.f16.f16.f16.f16 "
        "{%0,%1}, {%2,%3,%4,%5}, {%6,%7}, {%0,%1};\n"
        : "+r"(c[0]), "+r"(c[1])
        : "r"(a[0]), "r"(a[1]), "r"(a[2]), "r"(a[3]), "r"(b0), "r"(b1));
}

__device__ __forceinline__ void ldsm4t(uint32_t& r0, uint32_t& r1, uint32_t& r2, uint32_t& r3,
                                       uint32_t addr) {
    asm volatile("ldmatrix.sync.aligned.m8n8.x4.trans.shared.b16 {%0,%1,%2,%3}, [%4];\n"
                 : "=r"(r0), "=r"(r1), "=r"(r2), "=r"(r3)
                 : "r"(addr));
}

// Dual-tile f16-accum GEMM: C[h][8][2] = A[h](16x64) @ W(64x64), h=0,1.
// One ldmatrix B-fragment feeds MMAs of BOTH row halves (halves LDSM per row).
__device__ __forceinline__ void gemm64x2h(uint32_t C[2][8][2], const uint32_t A[2][4][4],
                                          const __half* W, int lane) {
#pragma unroll
    for (int h = 0; h < 2; h++)
#pragma unroll
        for (int nt = 0; nt < 8; nt++) { C[h][nt][0] = 0u; C[h][nt][1] = 0u; }

    uint32_t base = (uint32_t)__cvta_generic_to_shared(
        W + (lane & 15) * WST + ((lane & 16) ? 8 : 0));
#pragma unroll
    for (int nt2 = 0; nt2 < 4; nt2++) {
#pragma unroll
        for (int kb = 0; kb < 4; kb++) {
            uint32_t b0, b1, b2, b3;
            ldsm4t(b0, b1, b2, b3, base + (uint32_t)((kb * 16 * WST + nt2 * 16) * 2));
            mma16816h(C[0][nt2 * 2],     A[0][kb], b0, b1);
            mma16816h(C[0][nt2 * 2 + 1], A[0][kb], b2, b3);
            mma16816h(C[1][nt2 * 2],     A[1][kb], b0, b1);
            mma16816h(C[1][nt2 * 2 + 1], A[1][kb], b2, b3);
        }
    }
}

__device__ __forceinline__ void add_bias2h(uint32_t C[2][8][2], const uint32_t* pb, int tig) {
#pragma unroll
    for (int h = 0; h < 2; h++)
#pragma unroll
        for (int nt = 0; nt < 8; nt++) {
            uint32_t b = pb[nt * 4 + tig];
            C[h][nt][0] = hadd2u(C[h][nt][0], b);
            C[h][nt][1] = hadd2u(C[h][nt][1], b);
        }
}

// f16 C layout == A-fragment layout: repack is a register rename (+ optional tanh)
__device__ __forceinline__ void repack_tanh2h(const uint32_t C[2][8][2], uint32_t A[2][4][4]) {
#pragma unroll
    for (int h = 0; h < 2; h++)
#pragma unroll
        for (int kb = 0; kb < 4; kb++) {
            A[h][kb][0] = htanh2(C[h][2 * kb][0]);
            A[h][kb][1] = htanh2(C[h][2 * kb][1]);
            A[h][kb][2] = htanh2(C[h][2 * kb + 1][0]);
            A[h][kb][3] = htanh2(C[h][2 * kb + 1][1]);
        }
}
__device__ __forceinline__ void repack_id2h(const uint32_t C[2][8][2], uint32_t A[2][4][4]) {
#pragma unroll
    for (int h = 0; h < 2; h++)
#pragma unroll
        for (int kb = 0; kb < 4; kb++) {
            A[h][kb][0] = C[h][2 * kb][0];
            A[h][kb][1] = C[h][2 * kb][1];
            A[h][kb][2] = C[h][2 * kb + 1][0];
            A[h][kb][3] = C[h][2 * kb + 1][1];
        }
}

__global__ void __launch_bounds__(256, 1)
pinn_kernel(Params p) {
    extern __shared__ char smem_raw[];
    __half* smW = reinterpret_cast<__half*>(smem_raw);
    float* smF = reinterpret_cast<float*>(smem_raw + W_HALFS * 2);
    uint32_t* smPB = reinterpret_cast<uint32_t*>(smem_raw + W_HALFS * 2 + F32_FLOATS * 4);
    const int tid = threadIdx.x;

    // ---- fold in the pass-through copy (24576 floats = 6144 float4) ----
    if (blockIdx.x < 24) {
        int i = blockIdx.x * 256 + tid;
        int j = i & 1023;
        int m = i >> 10;
        const float* srcs[6] = {p.col0, p.col1, p.col2, p.row0, p.row1, p.row2};
        const float4* s4 = reinterpret_cast<const float4*>(srcs[m]) + j;
        reinterpret_cast<float4*>(p.out + p.B)[i] = *s4;
    }

    // ---- stage weights (fp32 -> fp16, padded stride) + scalars + packed biases ----
    {
        const float* gsrc[NMAT] = {p.m2_w, p.m3_w, p.a0_w, p.a1_w, p.a2_w,
                                   p.col0, p.col1, p.col2, p.row0, p.row1, p.row2};
#pragma unroll
        for (int m = 0; m < NMAT; m++) {
            const float* src = gsrc[m];
            __half* dst = smW + m * MAT_HALFS;
            for (int i = tid; i < 4096; i += 256)
                dst[(i >> 6) * WST + (i & 63)] = __float2half_rn(src[i]);
        }
        if (tid < 192) smF[F_M1W + tid] = p.m1_w[tid];
        if (tid < 128) smF[F_SW + tid] = p.start_w[tid];
        if (tid < 64) {
            smF[F_M1B + tid] = p.m1_b[tid];
            smF[F_SB + tid]  = p.start_b[tid];
            smF[F_EW  + tid] = p.end_w[tid];
        }
        if (tid < 32) {
            int nt = tid >> 2, tg = tid & 3;
            int j0 = nt * 8 + tg * 2;
            smPB[PB_M2 + tid]      = pack2(p.m2_b[j0], p.m2_b[j0 + 1]);
            smPB[PB_M3 + tid]      = pack2(p.m3_b[j0], p.m3_b[j0 + 1]);
            smPB[PB_A0 + tid]      = pack2(p.a0_b[j0], p.a0_b[j0 + 1]);
            smPB[PB_A0 + 32 + tid] = pack2(p.a1_b[j0], p.a1_b[j0 + 1]);
            smPB[PB_A0 + 64 + tid] = pack2(p.a2_b[j0], p.a2_b[j0 + 1]);
        }
    }
    __syncthreads();

    const int lane = tid & 31, warp = tid >> 5;
    const int g = lane >> 2, tig = lane & 3;
    const float eb = p.end_b[0];

    for (int tile = blockIdx.x; tile < p.ntiles; tile += gridDim.x) {
        const int rowbase = tile * 256 + warp * 32;   // 32 rows per warp

        uint32_t Mst[2][4][4];  // hypernet state (f16 A-frags)
        uint32_t A[2][4][4];    // main-net h (f16 A-frags)
        uint32_t C[2][8][2];    // f16x2 accumulators

        // ---- hypernet input layer: tanh([beta,nu,rho] @ m1_w + m1_b) ----
#pragma unroll
        for (int h = 0; h < 2; h++) {
            const int rlo = rowbase + h * 16 + g, rhi = rlo + 8;
            float b0 = p.beta[rlo], b1 = p.beta[rhi];
            float n0 = p.nu[rlo],   n1 = p.nu[rhi];
            float r0 = p.rho[rlo],  r1 = p.rho[rhi];
#pragma unroll
            for (int kb = 0; kb < 4; kb++) {
                int j0 = kb * 16 + tig * 2;
#pragma unroll
                for (int hf = 0; hf < 2; hf++) {
                    int j = j0 + hf * 8;
                    float w0a = smF[F_M1W + j],        w0b = smF[F_M1W + j + 1];
                    float w1a = smF[F_M1W + 64 + j],   w1b = smF[F_M1W + 64 + j + 1];
                    float w2a = smF[F_M1W + 128 + j],  w2b = smF[F_M1W + 128 + j + 1];
                    float ba  = smF[F_M1B + j],        bb  = smF[F_M1B + j + 1];
                    Mst[h][kb][hf * 2 + 0] = htanh2(pack2(b0 * w0a + n0 * w1a + r0 * w2a + ba,
                                                          b0 * w0b + n0 * w1b + r0 * w2b + bb));
                    Mst[h][kb][hf * 2 + 1] = htanh2(pack2(b1 * w0a + n1 * w1a + r1 * w2a + ba,
                                                          b1 * w0b + n1 * w1b + r1 * w2b + bb));
                }
            }
        }

        // m2, m3 (tanh)
        gemm64x2h(C, Mst, smW + M_M2 * MAT_HALFS, lane);
        add_bias2h(C, smPB + PB_M2, tig);
        repack_tanh2h(C, Mst);
        gemm64x2h(C, Mst, smW + M_M3 * MAT_HALFS, lane);
        add_bias2h(C, smPB + PB_M3, tig);
        repack_tanh2h(C, Mst);

        // ---- main net input layer: tanh([x,t] @ start_w + start_b) ----
#pragma unroll
        for (int h = 0; h < 2; h++) {
            const int rlo = rowbase + h * 16 + g, rhi = rlo + 8;
            float x0 = p.x[rlo], x1 = p.x[rhi];
            float t0 = p.t[rlo], t1 = p.t[rhi];
#pragma unroll
            for (int kb = 0; kb < 4; kb++) {
                int j0 = kb * 16 + tig * 2;
#pragma unroll
                for (int hf = 0; hf < 2; hf++) {
                    int j = j0 + hf * 8;
                    float w0a = smF[F_SW + j],      w0b = smF[F_SW + j + 1];
                    float w1a = smF[F_SW + 64 + j], w1b = smF[F_SW + 64 + j + 1];
                    float ba  = smF[F_SB + j],      bb  = smF[F_SB + j + 1];
                    A[h][kb][hf * 2 + 0] = htanh2(pack2(x0 * w0a + t0 * w1a + ba,
                                                        x0 * w0b + t0 * w1b + bb));
                    A[h][kb][hf * 2 + 1] = htanh2(pack2(x1 * w0a + t1 * w1a + ba,
                                                        x1 * w0b + t1 * w1b + bb));
                }
            }
        }

        // ---- 3x: alpha_l = relu(M @ a_l); h = tanh(((h @ col_l) * alpha_l) @ row_l) ----
#pragma unroll
        for (int l = 0; l < 3; l++) {
            uint32_t al[2][8][2];
            gemm64x2h(C, Mst, smW + (M_A0 + l) * MAT_HALFS, lane);
            add_bias2h(C, smPB + PB_A0 + 32 * l, tig);
#pragma unroll
            for (int h = 0; h < 2; h++)
#pragma unroll
                for (int nt = 0; nt < 8; nt++) {
                    al[h][nt][0] = hrelu2(C[h][nt][0]);
                    al[h][nt][1] = hrelu2(C[h][nt][1]);
                }

            gemm64x2h(C, A, smW + (M_C0 + l) * MAT_HALFS, lane);
#pragma unroll
            for (int h = 0; h < 2; h++)
#pragma unroll
                for (int nt = 0; nt < 8; nt++) {
                    C[h][nt][0] = hmul2u(C[h][nt][0], al[h][nt][0]);
                    C[h][nt][1] = hmul2u(C[h][nt][1], al[h][nt][1]);
                }
            repack_id2h(C, A);
            gemm64x2h(C, A, smW + (M_R0 + l) * MAT_HALFS, lane);
            repack_tanh2h(C, A);
        }

        // ---- out = h @ end_w + end_b (f32 dot) ----
#pragma unroll
        for (int h = 0; h < 2; h++) {
            const int rlo = rowbase + h * 16 + g, rhi = rlo + 8;
            float slo = 0.f, shi = 0.f;
#pragma unroll
            for (int kb = 0; kb < 4; kb++) {
                int j0 = kb * 16 + tig * 2;
                float2 f;
                f = unpack2(A[h][kb][0]); slo += f.x * smF[F_EW + j0]     + f.y * smF[F_EW + j0 + 1];
                f = unpack2(A[h][kb][1]); shi += f.x * smF[F_EW + j0]     + f.y * smF[F_EW + j0 + 1];
                f = unpack2(A[h][kb][2]); slo += f.x * smF[F_EW + j0 + 8] + f.y * smF[F_EW + j0 + 9];
                f = unpack2(A[h][kb][3]); shi += f.x * smF[F_EW + j0 + 8] + f.y * smF[F_EW + j0 + 9];
            }
            slo += __shfl_xor_sync(0xFFFFFFFFu, slo, 1);
            slo += __shfl_xor_sync(0xFFFFFFFFu, slo, 2);
            shi += __shfl_xor_sync(0xFFFFFFFFu, shi, 1);
            shi += __shfl_xor_sync(0xFFFFFFFFu, shi, 2);
            if (tig == 0) {
                p.out[rlo] = slo + eb;
                p.out[rhi] = shi + eb;
            }
        }
    }
}

extern "C" void kernel_launch(void* const* d_in, const int* in_sizes, int n_in,
                              void* d_out, int out_size) {
    (void)n_in; (void)out_size;
    Params p;
    p.x       = (const float*)d_in[0];
    p.t       = (const float*)d_in[1];
    p.beta    = (const float*)d_in[2];
    p.nu      = (const float*)d_in[3];
    p.rho     = (const float*)d_in[4];
    p.start_w = (const float*)d_in[5];
    p.start_b = (const float*)d_in[6];
    p.end_w   = (const float*)d_in[7];
    p.end_b   = (const float*)d_in[8];
    p.m1_w    = (const float*)d_in[9];
    p.m1_b    = (const float*)d_in[10];
    p.m2_w    = (const float*)d_in[11];
    p.m2_b    = (const float*)d_in[12];
    p.m3_w    = (const float*)d_in[13];
    p.m3_b    = (const float*)d_in[14];
    p.a0_w    = (const float*)d_in[15];
    p.a0_b    = (const float*)d_in[16];
    p.a1_w    = (const float*)d_in[17];
    p.a1_b    = (const float*)d_in[18];
    p.a2_w    = (const float*)d_in[19];
    p.a2_b    = (const float*)d_in[20];
    p.col0    = (const float*)d_in[21];
    p.col1    = (const float*)d_in[22];
    p.col2    = (const float*)d_in[23];
    p.row0    = (const float*)d_in[24];
    p.row1    = (const float*)d_in[25];
    p.row2    = (const float*)d_in[26];
    p.out     = (float*)d_out;

    p.B = in_sizes[0];
    p.ntiles = p.B / 256;   // 256 rows per CTA tile

    int dev = 0, nsm = 148;
    cudaGetDevice(&dev);
    cudaDeviceGetAttribute(&nsm, cudaDevAttrMultiProcessorCount, dev);
    int grid = nsm < 24 ? 24 : nsm;   // >=24 so the folded copy covers all 6 matrices
    if (grid > p.ntiles) grid = p.ntiles;

    cudaFuncSetAttribute(pinn_kernel, cudaFuncAttributeMaxDynamicSharedMemorySize, SMEM_BYTES);
    pinn_kernel<<<grid, 256, SMEM_BYTES>>>(p);
}

// round 9
// speedup vs baseline: 1.3209x; 1.0683x over previous
#include <cuda_runtime.h>
#include <cuda_fp16.h>
#include <stdint.h>

#define NTHREADS 384
#define TILE_ROWS 384                // 12 warps x 32 rows
#define WST 72                       // padded smem stride (halfs) -> conflict-free ldmatrix
#define MAT_HALFS (64 * WST)         // 4608 halfs per 64x64 matrix
#define NMAT 11
#define W_HALFS (NMAT * MAT_HALFS)
#define F32_FLOATS 512
#define PB_WORDS 160
#define SMEM_BYTES (W_HALFS * 2 + F32_FLOATS * 4 + PB_WORDS * 4)

// f32 scalar region offsets (floats)
#define F_M1W 0
#define F_M1B 192
#define F_SW  256
#define F_SB  384
#define F_EW  448
// packed f16x2 bias region offsets (uint32 words)
#define PB_M2 0
#define PB_M3 32
#define PB_A0 64     // +32 per alpha head

// matrix slots in smem
#define M_M2 0
#define M_M3 1
#define M_A0 2
#define M_A1 3
#define M_A2 4
#define M_C0 5
#define M_R0 8

struct Params {
    const float *x, *t, *beta, *nu, *rho;
    const float *start_w, *start_b, *end_w, *end_b;
    const float *m1_w, *m1_b, *m2_w, *m2_b, *m3_w, *m3_b;
    const float *a0_w, *a0_b, *a1_w, *a1_b, *a2_w, *a2_b;
    const float *col0, *col1, *col2, *row0, *row1, *row2;
    float* out;
    int ntiles;
    int B;
};

__device__ __forceinline__ uint32_t pack2(float lo, float hi) {
    __half2 h = __floats2half2_rn(lo, hi);
    return *reinterpret_cast<uint32_t*>(&h);
}
__device__ __forceinline__ float2 unpack2(uint32_t v) {
    __half2 h = *reinterpret_cast<__half2*>(&v);
    return __half22float2(h);
}
// HW tanh on packed f16x2
__device__ __forceinline__ uint32_t htanh2(uint32_t v) {
    uint32_t y;
    asm("tanh.approx.f16x2 %0, %1;" : "=r"(y) : "r"(v));
    return y;
}
__device__ __forceinline__ uint32_t hadd2u(uint32_t a, uint32_t b) {
    __half2 r = __hadd2(*reinterpret_cast<__half2*>(&a), *reinterpret_cast<__half2*>(&b));
    return *reinterpret_cast<uint32_t*>(&r);
}
__device__ __forceinline__ uint32_t hmul2u(uint32_t a, uint32_t b) {
    __half2 r = __hmul2(*reinterpret_cast<__half2*>(&a), *reinterpret_cast<__half2*>(&b));
    return *reinterpret_cast<uint32_t*>(&r);
}
__device__ __forceinline__ uint32_t hrelu2(uint32_t a) {
    __half2 z = __float2half2_rn(0.f);
    __half2 r = __hmax2(*reinterpret_cast<__half2*>(&a), z);
    return *reinterpret_cast<uint32_t*>(&r);
}

// f16-accumulator MMA
__device__ __forceinline__ void mma16816h(uint32_t* c, const uint32_t* a, uint32_t b0, uint32_t b1) {
    asm volatile(
        "mma.sync.aligned.m16n8k16.row.col.f16.f16.f16.f16 "
        "{%0,%1}, {%2,%3,%4,%5}, {%6,%7}, {%0,%1};\n"
        : "+r"(c[0]), "+r"(c[1])
        : "r"(a[0]), "r"(a[1]), "r"(a[2]), "r"(a[3]), "r"(b0), "r"(b1));
}

__device__ __forceinline__ void ldsm4t(uint32_t& r0, uint32_t& r1, uint32_t& r2, uint32_t& r3,
                                       uint32_t addr) {
    asm volatile("ldmatrix.sync.aligned.m8n8.x4.trans.shared.b16 {%0,%1,%2,%3}, [%4];\n"
                 : "=r"(r0), "=r"(r1), "=r"(r2), "=r"(r3)
                 : "r"(addr));
}

// Dual-tile f16-accum GEMM: C[h][8][2] = A[h](16x64) @ W(64x64), h=0,1.
__device__ __forceinline__ void gemm64x2h(uint32_t C[2][8][2], const uint32_t A[2][4][4],
                                          const __half* W, int lane) {
#pragma unroll
    for (int h = 0; h < 2; h++)
#pragma unroll
        for (int nt = 0; nt < 8; nt++) { C[h][nt][0] = 0u; C[h][nt][1] = 0u; }

    uint32_t base = (uint32_t)__cvta_generic_to_shared(
        W + (lane & 15) * WST + ((lane & 16) ? 8 : 0));
#pragma unroll
    for (int nt2 = 0; nt2 < 4; nt2++) {
#pragma unroll
        for (int kb = 0; kb < 4; kb++) {
            uint32_t b0, b1, b2, b3;
            ldsm4t(b0, b1, b2, b3, base + (uint32_t)((kb * 16 * WST + nt2 * 16) * 2));
            mma16816h(C[0][nt2 * 2],     A[0][kb], b0, b1);
            mma16816h(C[0][nt2 * 2 + 1], A[0][kb], b2, b3);
            mma16816h(C[1][nt2 * 2],     A[1][kb], b0, b1);
            mma16816h(C[1][nt2 * 2 + 1], A[1][kb], b2, b3);
        }
    }
}

__device__ __forceinline__ void add_bias2h(uint32_t C[2][8][2], const uint32_t* pb, int tig) {
#pragma unroll
    for (int h = 0; h < 2; h++)
#pragma unroll
        for (int nt = 0; nt < 8; nt++) {
            uint32_t b = pb[nt * 4 + tig];
            C[h][nt][0] = hadd2u(C[h][nt][0], b);
            C[h][nt][1] = hadd2u(C[h][nt][1], b);
        }
}

// f16 C layout == A-fragment layout: repack is a register rename (+ tanh)
__device__ __forceinline__ void repack_tanh2h(const uint32_t C[2][8][2], uint32_t A[2][4][4]) {
#pragma unroll
    for (int h = 0; h < 2; h++)
#pragma unroll
        for (int kb = 0; kb < 4; kb++) {
            A[h][kb][0] = htanh2(C[h][2 * kb][0]);
            A[h][kb][1] = htanh2(C[h][2 * kb][1]);
            A[h][kb][2] = htanh2(C[h][2 * kb + 1][0]);
            A[h][kb][3] = htanh2(C[h][2 * kb + 1][1]);
        }
}
__device__ __forceinline__ void repack_id2h(const uint32_t C[2][8][2], uint32_t A[2][4][4]) {
#pragma unroll
    for (int h = 0; h < 2; h++)
#pragma unroll
        for (int kb = 0; kb < 4; kb++) {
            A[h][kb][0] = C[h][2 * kb][0];
            A[h][kb][1] = C[h][2 * kb][1];
            A[h][kb][2] = C[h][2 * kb + 1][0];
            A[h][kb][3] = C[h][2 * kb + 1][1];
        }
}

__global__ void __launch_bounds__(NTHREADS, 1)
pinn_kernel(Params p) {
    extern __shared__ char smem_raw[];
    __half* smW = reinterpret_cast<__half*>(smem_raw);
    float* smF = reinterpret_cast<float*>(smem_raw + W_HALFS * 2);
    uint32_t* smPB = reinterpret_cast<uint32_t*>(smem_raw + W_HALFS * 2 + F32_FLOATS * 4);
    const int tid = threadIdx.x;

    // ---- fold in the pass-through copy (24576 floats = 6144 float4, 16 blocks x 384) ----
    if (blockIdx.x < 16) {
        int i = blockIdx.x * NTHREADS + tid;
        int j = i & 1023;
        int m = i >> 10;
        const float* srcs[6] = {p.col0, p.col1, p.col2, p.row0, p.row1, p.row2};
        const float4* s4 = reinterpret_cast<const float4*>(srcs[m]) + j;
        reinterpret_cast<float4*>(p.out + p.B)[i] = *s4;
    }

    // ---- stage weights (fp32 -> fp16, padded stride) + scalars + packed biases ----
    {
        const float* gsrc[NMAT] = {p.m2_w, p.m3_w, p.a0_w, p.a1_w, p.a2_w,
                                   p.col0, p.col1, p.col2, p.row0, p.row1, p.row2};
#pragma unroll
        for (int m = 0; m < NMAT; m++) {
            const float* src = gsrc[m];
            __half* dst = smW + m * MAT_HALFS;
            for (int i = tid; i < 4096; i += NTHREADS)
                dst[(i >> 6) * WST + (i & 63)] = __float2half_rn(src[i]);
        }
        if (tid < 192) smF[F_M1W + tid] = p.m1_w[tid];
        if (tid < 128) smF[F_SW + tid] = p.start_w[tid];
        if (tid < 64) {
            smF[F_M1B + tid] = p.m1_b[tid];
            smF[F_SB + tid]  = p.start_b[tid];
            smF[F_EW  + tid] = p.end_w[tid];
        }
        if (tid < 32) {
            int nt = tid >> 2, tg = tid & 3;
            int j0 = nt * 8 + tg * 2;
            smPB[PB_M2 + tid]      = pack2(p.m2_b[j0], p.m2_b[j0 + 1]);
            smPB[PB_M3 + tid]      = pack2(p.m3_b[j0], p.m3_b[j0 + 1]);
            smPB[PB_A0 + tid]      = pack2(p.a0_b[j0], p.a0_b[j0 + 1]);
            smPB[PB_A0 + 32 + tid] = pack2(p.a1_b[j0], p.a1_b[j0 + 1]);
            smPB[PB_A0 + 64 + tid] = pack2(p.a2_b[j0], p.a2_b[j0 + 1]);
        }
    }
    __syncthreads();

    const int lane = tid & 31, warp = tid >> 5;
    const int g = lane >> 2, tig = lane & 3;
    const float eb = p.end_b[0];

    for (int tile = blockIdx.x; tile < p.ntiles; tile += gridDim.x) {
        const int rowbase = tile * TILE_ROWS + warp * 32;   // 32 rows per warp
        if (rowbase >= p.B) continue;   // tail tile: whole warps drop out (no sync in loop)

        uint32_t Mst[2][4][4];  // hypernet state (f16 A-frags)
        uint32_t A[2][4][4];    // main-net h (f16 A-frags)
        uint32_t C[2][8][2];    // f16x2 accumulators

        // ---- hypernet input layer: tanh([beta,nu,rho] @ m1_w + m1_b) ----
#pragma unroll
        for (int h = 0; h < 2; h++) {
            const int rlo = rowbase + h * 16 + g, rhi = rlo + 8;
            float b0 = p.beta[rlo], b1 = p.beta[rhi];
            float n0 = p.nu[rlo],   n1 = p.nu[rhi];
            float r0 = p.rho[rlo],  r1 = p.rho[rhi];
#pragma unroll
            for (int kb = 0; kb < 4; kb++) {
                int j0 = kb * 16 + tig * 2;
#pragma unroll
                for (int hf = 0; hf < 2; hf++) {
                    int j = j0 + hf * 8;
                    float w0a = smF[F_M1W + j],        w0b = smF[F_M1W + j + 1];
                    float w1a = smF[F_M1W + 64 + j],   w1b = smF[F_M1W + 64 + j + 1];
                    float w2a = smF[F_M1W + 128 + j],  w2b = smF[F_M1W + 128 + j + 1];
                    float ba  = smF[F_M1B + j],        bb  = smF[F_M1B + j + 1];
                    Mst[h][kb][hf * 2 + 0] = htanh2(pack2(b0 * w0a + n0 * w1a + r0 * w2a + ba,
                                                          b0 * w0b + n0 * w1b + r0 * w2b + bb));
                    Mst[h][kb][hf * 2 + 1] = htanh2(pack2(b1 * w0a + n1 * w1a + r1 * w2a + ba,
                                                          b1 * w0b + n1 * w1b + r1 * w2b + bb));
                }
            }
        }

        // m2, m3 (tanh)
        gemm64x2h(C, Mst, smW + M_M2 * MAT_HALFS, lane);
        add_bias2h(C, smPB + PB_M2, tig);
        repack_tanh2h(C, Mst);
        gemm64x2h(C, Mst, smW + M_M3 * MAT_HALFS, lane);
        add_bias2h(C, smPB + PB_M3, tig);
        repack_tanh2h(C, Mst);

        // ---- main net input layer: tanh([x,t] @ start_w + start_b) ----
#pragma unroll
        for (int h = 0; h < 2; h++) {
            const int rlo = rowbase + h * 16 + g, rhi = rlo + 8;
            float x0 = p.x[rlo], x1 = p.x[rhi];
            float t0 = p.t[rlo], t1 = p.t[rhi];
#pragma unroll
            for (int kb = 0; kb < 4; kb++) {
                int j0 = kb * 16 + tig * 2;
#pragma unroll
                for (int hf = 0; hf < 2; hf++) {
                    int j = j0 + hf * 8;
                    float w0a = smF[F_SW + j],      w0b = smF[F_SW + j + 1];
                    float w1a = smF[F_SW + 64 + j], w1b = smF[F_SW + 64 + j + 1];
                    float ba  = smF[F_SB + j],      bb  = smF[F_SB + j + 1];
                    A[h][kb][hf * 2 + 0] = htanh2(pack2(x0 * w0a + t0 * w1a + ba,
                                                        x0 * w0b + t0 * w1b + bb));
                    A[h][kb][hf * 2 + 1] = htanh2(pack2(x1 * w0a + t1 * w1a + ba,
                                                        x1 * w0b + t1 * w1b + bb));
                }
            }
        }

        // ---- 3x: alpha_l = relu(M @ a_l); h = tanh(((h @ col_l) * alpha_l) @ row_l) ----
#pragma unroll
        for (int l = 0; l < 3; l++) {
            uint32_t al[2][8][2];
            gemm64x2h(C, Mst, smW + (M_A0 + l) * MAT_HALFS, lane);
            add_bias2h(C, smPB + PB_A0 + 32 * l, tig);
#pragma unroll
            for (int h = 0; h < 2; h++)
#pragma unroll
                for (int nt = 0; nt < 8; nt++) {
                    al[h][nt][0] = hrelu2(C[h][nt][0]);
                    al[h][nt][1] = hrelu2(C[h][nt][1]);
                }

            gemm64x2h(C, A, smW + (M_C0 + l) * MAT_HALFS, lane);
#pragma unroll
            for (int h = 0; h < 2; h++)
#pragma unroll
                for (int nt = 0; nt < 8; nt++) {
                    C[h][nt][0] = hmul2u(C[h][nt][0], al[h][nt][0]);
                    C[h][nt][1] = hmul2u(C[h][nt][1], al[h][nt][1]);
                }
            repack_id2h(C, A);
            gemm64x2h(C, A, smW + (M_R0 + l) * MAT_HALFS, lane);
            repack_tanh2h(C, A);
        }

        // ---- out = h @ end_w + end_b (f32 dot) ----
#pragma unroll
        for (int h = 0; h < 2; h++) {
            const int rlo = rowbase + h * 16 + g, rhi = rlo + 8;
            float slo = 0.f, shi = 0.f;
#pragma unroll
            for (int kb = 0; kb < 4; kb++) {
                int j0 = kb * 16 + tig * 2;
                float2 f;
                f = unpack2(A[h][kb][0]); slo += f.x * smF[F_EW + j0]     + f.y * smF[F_EW + j0 + 1];
                f = unpack2(A[h][kb][1]); shi += f.x * smF[F_EW + j0]     + f.y * smF[F_EW + j0 + 1];
                f = unpack2(A[h][kb][2]); slo += f.x * smF[F_EW + j0 + 8] + f.y * smF[F_EW + j0 + 9];
                f = unpack2(A[h][kb][3]); shi += f.x * smF[F_EW + j0 + 8] + f.y * smF[F_EW + j0 + 9];
            }
            slo += __shfl_xor_sync(0xFFFFFFFFu, slo, 1);
            slo += __shfl_xor_sync(0xFFFFFFFFu, slo, 2);
            shi += __shfl_xor_sync(0xFFFFFFFFu, shi, 1);
            shi += __shfl_xor_sync(0xFFFFFFFFu, shi, 2);
            if (tig == 0) {
                p.out[rlo] = slo + eb;
                p.out[rhi] = shi + eb;
            }
        }
    }
}

extern "C" void kernel_launch(void* const* d_in, const int* in_sizes, int n_in,
                              void* d_out, int out_size) {
    (void)n_in; (void)out_size;
    Params p;
    p.x       = (const float*)d_in[0];
    p.t       = (const float*)d_in[1];
    p.beta    = (const float*)d_in[2];
    p.nu      = (const float*)d_in[3];
    p.rho     = (const float*)d_in[4];
    p.start_w = (const float*)d_in[5];
    p.start_b = (const float*)d_in[6];
    p.end_w   = (const float*)d_in[7];
    p.end_b   = (const float*)d_in[8];
    p.m1_w    = (const float*)d_in[9];
    p.m1_b    = (const float*)d_in[10];
    p.m2_w    = (const float*)d_in[11];
    p.m2_b    = (const float*)d_in[12];
    p.m3_w    = (const float*)d_in[13];
    p.m3_b    = (const float*)d_in[14];
    p.a0_w    = (const float*)d_in[15];
    p.a0_b    = (const float*)d_in[16];
    p.a1_w    = (const float*)d_in[17];
    p.a1_b    = (const float*)d_in[18];
    p.a2_w    = (const float*)d_in[19];
    p.a2_b    = (const float*)d_in[20];
    p.col0    = (const float*)d_in[21];
    p.col1    = (const float*)d_in[22];
    p.col2    = (const float*)d_in[23];
    p.row0    = (const float*)d_in[24];
    p.row1    = (const float*)d_in[25];
    p.row2    = (const float*)d_in[26];
    p.out     = (float*)d_out;

    p.B = in_sizes[0];
    p.ntiles = (p.B + TILE_ROWS - 1) / TILE_ROWS;

    int dev = 0, nsm = 148;
    cudaGetDevice(&dev);
    cudaDeviceGetAttribute(&nsm, cudaDevAttrMultiProcessorCount, dev);
    int grid = nsm < 16 ? 16 : nsm;   // >=16 so the folded copy covers all 6 matrices
    if (grid > p.ntiles) grid = p.ntiles;

    cudaFuncSetAttribute(pinn_kernel, cudaFuncAttributeMaxDynamicSharedMemorySize, SMEM_BYTES);
    pinn_kernel<<<grid, NTHREADS, SMEM_BYTES>>>(p);
}